// round 3
// baseline (speedup 1.0000x reference)
#include <cuda_runtime.h>
#include <cstddef>

// Problem constants
#define BB  2
#define LL  2048
#define DD  1024
#define HH  16
#define HD  64
#define NBH (BB*HH)          // 32
#define QKV_ELEMS (BB*HH*LL*HD)   // 4,194,304 per tensor

// Scratch (static device globals; no allocation allowed)
__device__ float g_q[QKV_ELEMS];
__device__ float g_k[QKV_ELEMS];
__device__ float g_v[QKV_ELEMS];
__device__ float g_attn[BB*LL*DD];   // attention out in [B*L, H*HD] (concat) layout

// ---------------------------------------------------------------------------
// Kernel 1: fused per-head QKV projection, register-prefetch double buffered.
//   q[b,h,l,e] = sum_d x[b,l,d] * Wq[h,d,e]   (same for k,v)
// Grid: (B*L/64, H). Block 256 = 16x16 threads, 4x4 micro-tile per output
// (48 accumulators). x tile loaded once per k-chunk, reused for all three
// weights. K-chunk = 32. Next chunk's LDGs issued before compute so their
// latency hides behind the 1536 FMAs of the current chunk.
// ---------------------------------------------------------------------------
__global__ __launch_bounds__(256, 2)
void qkv_kernel(const float* __restrict__ x,
                const float* __restrict__ Wq,
                const float* __restrict__ Wk,
                const float* __restrict__ Wv)
{
    __shared__ __align__(16) float xs[32][68];     // x transposed: [k][row]
    __shared__ __align__(16) float wqs[32][64];    // [k][e]
    __shared__ __align__(16) float wks[32][64];
    __shared__ __align__(16) float wvs[32][64];

    const int h  = blockIdx.y;
    const int r0 = blockIdx.x * 64;          // global row in [0, B*L)
    const int tid = threadIdx.x;
    const int tx = tid & 15, ty = tid >> 4;

    float aq[4][4], ak[4][4], av[4][4];
#pragma unroll
    for (int i = 0; i < 4; i++)
#pragma unroll
        for (int j = 0; j < 4; j++) { aq[i][j]=0.f; ak[i][j]=0.f; av[i][j]=0.f; }

    const int lrow = tid >> 2;               // 0..63
    const int lk   = (tid & 3) * 4;          // 0,4,8,12 (+16 for second half)
    const int wkk  = tid >> 4;               // 0..15    (+16 for second half)
    const int we   = (tid & 15) * 4;         // 0..60

    float4 rx[2], rq[2], rk[2], rv[2];

    // prologue: load chunk 0 into registers
#pragma unroll
    for (int hlf = 0; hlf < 2; hlf++) {
        rx[hlf] = *(const float4*)&x[(size_t)(r0 + lrow) * DD + lk + hlf * 16];
        size_t wo = ((size_t)h * DD + wkk + hlf * 16) * HD + we;
        rq[hlf] = *(const float4*)&Wq[wo];
        rk[hlf] = *(const float4*)&Wk[wo];
        rv[hlf] = *(const float4*)&Wv[wo];
    }

    for (int k0 = 0; k0 < DD; k0 += 32) {
        // commit prefetched registers to smem
#pragma unroll
        for (int hlf = 0; hlf < 2; hlf++) {
            const int kx = lk + hlf * 16;
            xs[kx + 0][lrow] = rx[hlf].x;
            xs[kx + 1][lrow] = rx[hlf].y;
            xs[kx + 2][lrow] = rx[hlf].z;
            xs[kx + 3][lrow] = rx[hlf].w;
            const int kw = wkk + hlf * 16;
            *(float4*)&wqs[kw][we] = rq[hlf];
            *(float4*)&wks[kw][we] = rk[hlf];
            *(float4*)&wvs[kw][we] = rv[hlf];
        }
        __syncthreads();

        // prefetch next chunk into registers (overlaps with compute below)
        const int kn = k0 + 32;
        if (kn < DD) {
#pragma unroll
            for (int hlf = 0; hlf < 2; hlf++) {
                rx[hlf] = *(const float4*)&x[(size_t)(r0 + lrow) * DD + kn + lk + hlf * 16];
                size_t wo = ((size_t)h * DD + kn + wkk + hlf * 16) * HD + we;
                rq[hlf] = *(const float4*)&Wq[wo];
                rk[hlf] = *(const float4*)&Wk[wo];
                rv[hlf] = *(const float4*)&Wv[wo];
            }
        }

#pragma unroll 8
        for (int kk = 0; kk < 32; kk++) {
            const float4 a4 = *(const float4*)&xs[kk][ty * 4];
            const float4 q4 = *(const float4*)&wqs[kk][tx * 4];
            const float4 k4 = *(const float4*)&wks[kk][tx * 4];
            const float4 v4 = *(const float4*)&wvs[kk][tx * 4];
            const float a[4]  = {a4.x, a4.y, a4.z, a4.w};
            const float bq[4] = {q4.x, q4.y, q4.z, q4.w};
            const float bk[4] = {k4.x, k4.y, k4.z, k4.w};
            const float bv[4] = {v4.x, v4.y, v4.z, v4.w};
#pragma unroll
            for (int i = 0; i < 4; i++)
#pragma unroll
                for (int j = 0; j < 4; j++) {
                    aq[i][j] = fmaf(a[i], bq[j], aq[i][j]);
                    ak[i][j] = fmaf(a[i], bk[j], ak[i][j]);
                    av[i][j] = fmaf(a[i], bv[j], av[i][j]);
                }
        }
        __syncthreads();   // all reads done before next commit overwrites smem
    }

    // epilogue: store to [b,h,l,e] layout
    const int b = r0 / LL;
    const int l = r0 - b * LL;
    const size_t base = ((size_t)(b * HH + h) * LL + l) * HD + tx * 4;
#pragma unroll
    for (int i = 0; i < 4; i++) {
        size_t off = base + (size_t)(ty * 4 + i) * HD;
        *(float4*)&g_q[off] = make_float4(aq[i][0], aq[i][1], aq[i][2], aq[i][3]);
        *(float4*)&g_k[off] = make_float4(ak[i][0], ak[i][1], ak[i][2], ak[i][3]);
        *(float4*)&g_v[off] = make_float4(av[i][0], av[i][1], av[i][2], av[i][3]);
    }
}

// ---------------------------------------------------------------------------
// Kernel 2: causal flash attention, per (b,h) head and 64-query tile.
// Grid: (L/64, B*H). Block 256 = 16x16 threads.
// smem: Qt/Kt (e-major, transposed), Vs (kv-major), Pt (kv-major transposed P).
// Softmax stats kept in registers; row reductions via shfl across the 16
// tx-lanes sharing each row group. Scale 1/8 folded into Q load.
// ---------------------------------------------------------------------------
#define ATTN_SMEM (4 * 64 * 68 * 4)

__global__ __launch_bounds__(256, 2)
void attn_kernel()
{
    extern __shared__ __align__(16) float sm[];
    float* Qt = sm;                 // [64e][68] : Qt[e][q]
    float* Kt = sm + 64 * 68;       // [64e][68] : Kt[e][kv]
    float* Vs = sm + 2 * 64 * 68;   // [64kv][68]: Vs[kv][e]
    float* Pt = sm + 3 * 64 * 68;   // [64kv][68]: Pt[kv][q]

    const int qt = blockIdx.x;          // query tile
    const int bh = blockIdx.y;          // b*H + h
    const int q0 = qt * 64;
    const float* Qg = g_q + (size_t)bh * LL * HD;
    const float* Kg = g_k + (size_t)bh * LL * HD;
    const float* Vg = g_v + (size_t)bh * LL * HD;

    const int tid = threadIdx.x;
    const int tx = tid & 15, ty = tid >> 4;
    const int trow = tid >> 2;           // 0..63
    const int te0  = (tid & 3) * 16;     // 0,16,32,48

    // load Q tile transposed, pre-scaled by 1/sqrt(HD) = 0.125
    {
#pragma unroll
        for (int u = 0; u < 4; u++) {
            float4 v = *(const float4*)&Qg[(size_t)(q0 + trow) * HD + te0 + u * 4];
            Qt[(te0 + u * 4 + 0) * 68 + trow] = v.x * 0.125f;
            Qt[(te0 + u * 4 + 1) * 68 + trow] = v.y * 0.125f;
            Qt[(te0 + u * 4 + 2) * 68 + trow] = v.z * 0.125f;
            Qt[(te0 + u * 4 + 3) * 68 + trow] = v.w * 0.125f;
        }
    }

    float o[4][4];
    float mrow[4], lrow[4];
#pragma unroll
    for (int i = 0; i < 4; i++) {
        mrow[i] = -1e30f; lrow[i] = 0.f;
#pragma unroll
        for (int j = 0; j < 4; j++) o[i][j] = 0.f;
    }

    for (int kt = 0; kt <= qt; kt++) {
        __syncthreads();   // protects Qt on first iter; Kt/Vs/Pt reuse on later
        const int k0 = kt * 64;
        // load K transposed
#pragma unroll
        for (int u = 0; u < 4; u++) {
            float4 v = *(const float4*)&Kg[(size_t)(k0 + trow) * HD + te0 + u * 4];
            Kt[(te0 + u * 4 + 0) * 68 + trow] = v.x;
            Kt[(te0 + u * 4 + 1) * 68 + trow] = v.y;
            Kt[(te0 + u * 4 + 2) * 68 + trow] = v.z;
            Kt[(te0 + u * 4 + 3) * 68 + trow] = v.w;
        }
        // load V (tile is a contiguous 16KB block in gmem -> perfectly coalesced)
#pragma unroll
        for (int p = 0; p < 4; p++) {
            int lin = tid * 4 + p * 1024;
            int r = lin >> 6, e = lin & 63;
            *(float4*)&Vs[r * 68 + e] = *(const float4*)&Vg[(size_t)k0 * HD + lin];
        }
        __syncthreads();

        // S = Q K^T (pre-scaled)
        float s[4][4];
#pragma unroll
        for (int i = 0; i < 4; i++)
#pragma unroll
            for (int j = 0; j < 4; j++) s[i][j] = 0.f;
#pragma unroll 8
        for (int e = 0; e < 64; e++) {
            const float4 a4 = *(const float4*)&Qt[e * 68 + ty * 4];
            const float4 b4 = *(const float4*)&Kt[e * 68 + tx * 4];
            const float a[4] = {a4.x, a4.y, a4.z, a4.w};
            const float b[4] = {b4.x, b4.y, b4.z, b4.w};
#pragma unroll
            for (int i = 0; i < 4; i++)
#pragma unroll
                for (int j = 0; j < 4; j++)
                    s[i][j] = fmaf(a[i], b[j], s[i][j]);
        }

        // causal mask on diagonal tile (q0 == k0 here)
        if (kt == qt) {
#pragma unroll
            for (int i = 0; i < 4; i++)
#pragma unroll
                for (int j = 0; j < 4; j++)
                    if (tx * 4 + j > ty * 4 + i) s[i][j] = -1e30f;
        }

        // online softmax update (stats replicated across the 16 tx lanes)
        float ps[4][4];
#pragma unroll
        for (int i = 0; i < 4; i++) {
            float mt = fmaxf(fmaxf(s[i][0], s[i][1]), fmaxf(s[i][2], s[i][3]));
            mt = fmaxf(mt, __shfl_xor_sync(0xffffffffu, mt, 8));
            mt = fmaxf(mt, __shfl_xor_sync(0xffffffffu, mt, 4));
            mt = fmaxf(mt, __shfl_xor_sync(0xffffffffu, mt, 2));
            mt = fmaxf(mt, __shfl_xor_sync(0xffffffffu, mt, 1));
            const float mnew = fmaxf(mrow[i], mt);
            const float alpha = __expf(mrow[i] - mnew);
            mrow[i] = mnew;
            float rs = 0.f;
#pragma unroll
            for (int j = 0; j < 4; j++) {
                ps[i][j] = __expf(s[i][j] - mnew);
                rs += ps[i][j];
            }
            rs += __shfl_xor_sync(0xffffffffu, rs, 8);
            rs += __shfl_xor_sync(0xffffffffu, rs, 4);
            rs += __shfl_xor_sync(0xffffffffu, rs, 2);
            rs += __shfl_xor_sync(0xffffffffu, rs, 1);
            lrow[i] = lrow[i] * alpha + rs;
#pragma unroll
            for (int j = 0; j < 4; j++) o[i][j] *= alpha;
        }

        // write P transposed: Pt[kv][q], float4 over the 4 q-rows
#pragma unroll
        for (int j = 0; j < 4; j++) {
            float4 pv = make_float4(ps[0][j], ps[1][j], ps[2][j], ps[3][j]);
            *(float4*)&Pt[(tx * 4 + j) * 68 + ty * 4] = pv;
        }
        __syncthreads();

        // O += P V
#pragma unroll 8
        for (int kv = 0; kv < 64; kv++) {
            const float4 a4 = *(const float4*)&Pt[kv * 68 + ty * 4];
            const float4 b4 = *(const float4*)&Vs[kv * 68 + tx * 4];
            const float a[4] = {a4.x, a4.y, a4.z, a4.w};
            const float b[4] = {b4.x, b4.y, b4.z, b4.w};
#pragma unroll
            for (int i = 0; i < 4; i++)
#pragma unroll
                for (int j = 0; j < 4; j++)
                    o[i][j] = fmaf(a[i], b[j], o[i][j]);
        }
    }

    // epilogue: normalize and write directly into concat layout [B*L, H*HD]
    const int b = bh / HH, h = bh - b * HH;
#pragma unroll
    for (int i = 0; i < 4; i++) {
        const float inv = 1.0f / lrow[i];
        size_t off = ((size_t)b * LL + q0 + ty * 4 + i) * DD + h * HD + tx * 4;
        *(float4*)&g_attn[off] =
            make_float4(o[i][0] * inv, o[i][1] * inv, o[i][2] * inv, o[i][3] * inv);
    }
}

// ---------------------------------------------------------------------------
// Kernel 3: output projection  out = g_attn @ Wo   ([4096,1024] x [1024,1024])
// Grid: (B*L/64, D/64). Same skeleton as kernel 1, register-prefetch
// double buffered, K-chunk = 32.
// ---------------------------------------------------------------------------
__global__ __launch_bounds__(256, 2)
void oproj_kernel(const float* __restrict__ Wo, float* __restrict__ out)
{
    __shared__ __align__(16) float as_[32][68];   // A transposed: [k][row]
    __shared__ __align__(16) float bs[32][64];    // [k][e]

    const int r0 = blockIdx.x * 64;
    const int e0 = blockIdx.y * 64;
    const int tid = threadIdx.x;
    const int tx = tid & 15, ty = tid >> 4;

    float acc[4][4];
#pragma unroll
    for (int i = 0; i < 4; i++)
#pragma unroll
        for (int j = 0; j < 4; j++) acc[i][j] = 0.f;

    const int lrow = tid >> 2;
    const int lk   = (tid & 3) * 4;
    const int wkk  = tid >> 4;
    const int we   = (tid & 15) * 4;

    float4 ra[2], rb[2];
#pragma unroll
    for (int hlf = 0; hlf < 2; hlf++) {
        ra[hlf] = *(const float4*)&g_attn[(size_t)(r0 + lrow) * DD + lk + hlf * 16];
        rb[hlf] = *(const float4*)&Wo[(size_t)(wkk + hlf * 16) * DD + e0 + we];
    }

    for (int k0 = 0; k0 < DD; k0 += 32) {
#pragma unroll
        for (int hlf = 0; hlf < 2; hlf++) {
            const int ka = lk + hlf * 16;
            as_[ka + 0][lrow] = ra[hlf].x;
            as_[ka + 1][lrow] = ra[hlf].y;
            as_[ka + 2][lrow] = ra[hlf].z;
            as_[ka + 3][lrow] = ra[hlf].w;
            *(float4*)&bs[wkk + hlf * 16][we] = rb[hlf];
        }
        __syncthreads();

        const int kn = k0 + 32;
        if (kn < DD) {
#pragma unroll
            for (int hlf = 0; hlf < 2; hlf++) {
                ra[hlf] = *(const float4*)&g_attn[(size_t)(r0 + lrow) * DD + kn + lk + hlf * 16];
                rb[hlf] = *(const float4*)&Wo[(size_t)(kn + wkk + hlf * 16) * DD + e0 + we];
            }
        }

#pragma unroll 8
        for (int kk = 0; kk < 32; kk++) {
            const float4 a4 = *(const float4*)&as_[kk][ty * 4];
            const float4 b4 = *(const float4*)&bs[kk][tx * 4];
            const float a[4] = {a4.x, a4.y, a4.z, a4.w};
            const float b[4] = {b4.x, b4.y, b4.z, b4.w};
#pragma unroll
            for (int i = 0; i < 4; i++)
#pragma unroll
                for (int j = 0; j < 4; j++)
                    acc[i][j] = fmaf(a[i], b[j], acc[i][j]);
        }
        __syncthreads();
    }

#pragma unroll
    for (int i = 0; i < 4; i++) {
        size_t off = (size_t)(r0 + ty * 4 + i) * DD + e0 + tx * 4;
        *(float4*)&out[off] = make_float4(acc[i][0], acc[i][1], acc[i][2], acc[i][3]);
    }
}

// ---------------------------------------------------------------------------
extern "C" void kernel_launch(void* const* d_in, const int* in_sizes, int n_in,
                              void* d_out, int out_size)
{
    (void)in_sizes; (void)n_in; (void)out_size;
    const float* x  = (const float*)d_in[0];
    const float* Wq = (const float*)d_in[1];
    const float* Wk = (const float*)d_in[2];
    const float* Wv = (const float*)d_in[3];
    const float* Wo = (const float*)d_in[4];
    float* out = (float*)d_out;

    qkv_kernel<<<dim3((BB * LL) / 64, HH), 256>>>(x, Wq, Wk, Wv);

    cudaFuncSetAttribute(attn_kernel,
                         cudaFuncAttributeMaxDynamicSharedMemorySize, ATTN_SMEM);
    attn_kernel<<<dim3(LL / 64, NBH), 256, ATTN_SMEM>>>();

    oproj_kernel<<<dim3((BB * LL) / 64, DD / 64), 256>>>(Wo, out);
}